// round 9
// baseline (speedup 1.0000x reference)
#include <cuda_runtime.h>
#include <cuda_fp16.h>
#include <math.h>

#define MAXN 50048
#define MAXE 1605632
#define NH 8
#define OD 16

// ---- device scratch ----
__device__ __half g_KV [MAXN * 256];    // [node][K(128) | V(128)] fp16
__device__ float  g_Qs [MAXN * 16];     // Qsum fp32
__device__ float  g_W  [256 * 128];     // Kw | Vw
__device__ float  g_b  [256];
__device__ float  g_Qsw[16 * 128];      // head-reduced Q weights
__device__ float  g_qb [16];
__device__ int    g_cnt[MAXN];
__device__ int    g_cur[MAXN];
__device__ int    g_ofs[MAXN + 1];
__device__ int    g_part[256];
__device__ int    g_adj[MAXE];

// ------------------------------------------------------------------
// Kernel: assemble weights
// ------------------------------------------------------------------
__global__ void prep_kernel(const float* __restrict__ Qw, const float* __restrict__ Qb,
                            const float* __restrict__ Kw, const float* __restrict__ Kb,
                            const float* __restrict__ Vw, const float* __restrict__ Vb)
{
    int t = blockIdx.x * blockDim.x + threadIdx.x;
    if (t < 128 * 128) {
        g_W[t]             = Kw[t];
        g_W[128 * 128 + t] = Vw[t];
    }
    if (t < 16 * 128) {
        int d = t / 128, c = t % 128;
        float s = 0.f;
        #pragma unroll
        for (int hh = 0; hh < NH; hh++) s += Qw[(hh * OD + d) * 128 + c];
        g_Qsw[t] = s;
    }
    if (t < 128) { g_b[t] = Kb[t]; g_b[128 + t] = Vb[t]; }
    if (t < 16) {
        float s = 0.f;
        #pragma unroll
        for (int hh = 0; hh < NH; hh++) s += Qb[hh * OD + t];
        g_qb[t] = s;
    }
}

// ------------------------------------------------------------------
// Kernel: zero CSR counters
// ------------------------------------------------------------------
__global__ void zero_cnt_kernel(int N)
{
    int i = blockIdx.x * blockDim.x + threadIdx.x;
    if (i < N) { g_cnt[i] = 0; g_cur[i] = 0; }
}

// ------------------------------------------------------------------
// Fused kernel:
//   y==0 : GEMM cols 0..127 (K)  + Qsum 16 cols (reuses A tile in smem)
//   y==1 : GEMM cols 128..255 (V)
//   y==2 : edge counting (overlaps with FMA-bound GEMM blocks)
// ------------------------------------------------------------------
#define BM 128
#define BN 128
#define BK 8
__global__ __launch_bounds__(256) void gemm_kernel(const float* __restrict__ h,
                                                   const int* __restrict__ dst,
                                                   int N, int nE)
{
    if (blockIdx.y == 2) {
        int t = blockIdx.x * 256 + threadIdx.x;
        int stride4 = gridDim.x * 256 * 4;
        for (int e4 = t * 4; e4 < nE; e4 += stride4) {
            if (e4 + 4 <= nE) {
                int4 d4 = *reinterpret_cast<const int4*>(dst + e4);
                atomicAdd(&g_cnt[d4.x], 1); atomicAdd(&g_cnt[d4.y], 1);
                atomicAdd(&g_cnt[d4.z], 1); atomicAdd(&g_cnt[d4.w], 1);
            } else {
                for (int e = e4; e < nE; e++) atomicAdd(&g_cnt[dst[e]], 1);
            }
        }
        return;
    }

    __shared__ __align__(16) float As[BK][BM + 4];
    __shared__ __align__(16) float Bs[BK][BN + 4];
    __shared__ float Qb_s[BK][16];

    int tid = threadIdx.x;
    int tx = tid & 15;
    int ty = tid >> 4;
    int n0 = blockIdx.x * BM;
    int o0 = blockIdx.y * BN;
    bool doq = (blockIdx.y == 0);

    int lrow = tid >> 1;
    int lk   = (tid & 1) * 4;

    unsigned long long acc2[8][4];
    float acc_q[8];
    #pragma unroll
    for (int i = 0; i < 8; i++) {
        acc_q[i] = 0.f;
        #pragma unroll
        for (int jj = 0; jj < 4; jj++) acc2[i][jj] = 0ull;
    }

    int an = n0 + lrow; if (an >= N) an = N - 1;
    const float* aptr = h   + (size_t)an * 128 + lk;
    const float* bptr = g_W + (size_t)(o0 + lrow) * 128 + lk;

    for (int k0 = 0; k0 < 128; k0 += BK) {
        float4 av = *reinterpret_cast<const float4*>(aptr + k0);
        float4 bv = *reinterpret_cast<const float4*>(bptr + k0);
        As[lk + 0][lrow] = av.x; As[lk + 1][lrow] = av.y;
        As[lk + 2][lrow] = av.z; As[lk + 3][lrow] = av.w;
        Bs[lk + 0][lrow] = bv.x; Bs[lk + 1][lrow] = bv.y;
        Bs[lk + 2][lrow] = bv.z; Bs[lk + 3][lrow] = bv.w;
        if (doq && tid < 128) {
            int d = tid >> 3, kk = tid & 7;
            Qb_s[kk][d] = g_Qsw[d * 128 + k0 + kk];
        }
        __syncthreads();

        #pragma unroll
        for (int kk = 0; kk < BK; kk++) {
            float4 a0 = *reinterpret_cast<const float4*>(&As[kk][ty * 4]);
            float4 a1 = *reinterpret_cast<const float4*>(&As[kk][64 + ty * 4]);
            ulonglong2 bA = *reinterpret_cast<const ulonglong2*>(&Bs[kk][tx * 4]);
            ulonglong2 bB = *reinterpret_cast<const ulonglong2*>(&Bs[kk][64 + tx * 4]);
            unsigned long long B2[4] = { bA.x, bA.y, bB.x, bB.y };
            float aval[8] = { a0.x, a0.y, a0.z, a0.w, a1.x, a1.y, a1.z, a1.w };
            unsigned long long A2[8];
            #pragma unroll
            for (int i = 0; i < 8; i++)
                asm("mov.b64 %0, {%1, %1};" : "=l"(A2[i]) : "f"(aval[i]));
            #pragma unroll
            for (int i = 0; i < 8; i++)
                #pragma unroll
                for (int jj = 0; jj < 4; jj++)
                    asm("fma.rn.f32x2 %0, %1, %2, %0;"
                        : "+l"(acc2[i][jj]) : "l"(A2[i]), "l"(B2[jj]));
            if (doq) {
                float bq = Qb_s[kk][tx];
                #pragma unroll
                for (int i = 0; i < 8; i++) acc_q[i] = fmaf(aval[i], bq, acc_q[i]);
            }
        }
        __syncthreads();
    }

    #pragma unroll
    for (int i = 0; i < 8; i++) {
        int n = n0 + ((i < 4) ? (ty * 4 + i) : (64 + ty * 4 + (i - 4)));
        if (n >= N) continue;
        #pragma unroll
        for (int jj = 0; jj < 4; jj++) {
            int jb = (jj < 2) ? (tx * 4 + 2 * jj) : (64 + tx * 4 + 2 * (jj - 2));
            int o = o0 + jb;
            float lo, hi;
            asm("mov.b64 {%0, %1}, %2;" : "=f"(lo), "=f"(hi) : "l"(acc2[i][jj]));
            lo += g_b[o];
            hi += g_b[o + 1];
            *reinterpret_cast<__half2*>(&g_KV[(size_t)n * 256 + o]) =
                __floats2half2_rn(lo, hi);
        }
        if (doq) g_Qs[n * 16 + tx] = acc_q[i] + g_qb[tx];
    }
}

// ------------------------------------------------------------------
// CSR scan + fill
// ------------------------------------------------------------------
__global__ void scan_a_kernel(int N)
{
    __shared__ int sm[256];
    int tid = threadIdx.x;
    int i = blockIdx.x * 256 + tid;
    int v = (i < N) ? g_cnt[i] : 0;
    sm[tid] = v; __syncthreads();
    #pragma unroll
    for (int off = 1; off < 256; off <<= 1) {
        int t = (tid >= off) ? sm[tid - off] : 0;
        __syncthreads();
        sm[tid] += t;
        __syncthreads();
    }
    if (i < N) g_ofs[i] = sm[tid] - v;
    if (tid == 255) g_part[blockIdx.x] = sm[255];
}

__global__ void scan_b_kernel(int nb)
{
    __shared__ int sm[256];
    int tid = threadIdx.x;
    int v = (tid < nb) ? g_part[tid] : 0;
    sm[tid] = v; __syncthreads();
    #pragma unroll
    for (int off = 1; off < 256; off <<= 1) {
        int t = (tid >= off) ? sm[tid - off] : 0;
        __syncthreads();
        sm[tid] += t;
        __syncthreads();
    }
    if (tid < nb) g_part[tid] = sm[tid] - v;
}

__global__ void scan_c_kernel(int N, int nE)
{
    int i = blockIdx.x * 256 + threadIdx.x;
    if (i < N) g_ofs[i] += g_part[blockIdx.x];
    if (i == 0) g_ofs[N] = nE;
}

__global__ void fill_kernel(const int* __restrict__ src, const int* __restrict__ dst, int nE)
{
    int e = blockIdx.x * blockDim.x + threadIdx.x;
    if (e < nE) {
        int d = dst[e];
        int p = g_ofs[d] + atomicAdd(&g_cur[d], 1);
        g_adj[p] = src[e];
    }
}

// ------------------------------------------------------------------
// Gather: one warp per dst node. Single uint4 load per edge:
// lanes 0-15 hold K (lane l: head l/2, dims (l&1)*8..+8),
// lanes 16-31 hold V (m=l-16: head m/2, dims (m&1)*8..+8).
// ------------------------------------------------------------------
__global__ __launch_bounds__(256) void gather_kernel(float* __restrict__ out, int N)
{
    int n    = (blockIdx.x * blockDim.x + threadIdx.x) >> 5;
    int lane = threadIdx.x & 31;
    if (n >= N) return;

    const float4* qp = reinterpret_cast<const float4*>(g_Qs + n * 16 + (lane & 1) * 8);
    float4 q0 = qp[0], q1 = qp[1];

    float a0=0.f,a1=0.f,a2=0.f,a3=0.f,a4=0.f,a5=0.f,a6=0.f,a7=0.f;
    float z = 0.f;

    auto proc = [&](int s) {
        uint4 r = *reinterpret_cast<const uint4*>(g_KV + (size_t)s * 256 + lane * 8);
        float2 c0 = __half22float2(*reinterpret_cast<__half2*>(&r.x));
        float2 c1 = __half22float2(*reinterpret_cast<__half2*>(&r.y));
        float2 c2 = __half22float2(*reinterpret_cast<__half2*>(&r.z));
        float2 c3 = __half22float2(*reinterpret_cast<__half2*>(&r.w));
        float p = c0.x*q0.x + c0.y*q0.y + c1.x*q0.z + c1.y*q0.w
                + c2.x*q1.x + c2.y*q1.y + c3.x*q1.z + c3.y*q1.w;
        p += __shfl_xor_sync(0xffffffffu, p, 1);          // pair-sum -> head score (K lanes)
        p  = __shfl_sync(0xffffffffu, p, lane & 15);      // broadcast K-side to V-side
        float sc = __expf(fminf(fmaxf(p * 0.25f, -5.f), 5.f));
        a0 = fmaf(sc, c0.x, a0); a1 = fmaf(sc, c0.y, a1);
        a2 = fmaf(sc, c1.x, a2); a3 = fmaf(sc, c1.y, a3);
        a4 = fmaf(sc, c2.x, a4); a5 = fmaf(sc, c2.y, a5);
        a6 = fmaf(sc, c3.x, a6); a7 = fmaf(sc, c3.y, a7);
        z += sc;
    };

    proc(n);    // self-loop

    int beg = g_ofs[n], end = g_ofs[n + 1];
    for (int base = beg; base < end; base += 32) {
        int rem = end - base;
        int sv = (lane < rem) ? g_adj[base + lane] : 0;
        int m = min(rem, 32);
        #pragma unroll 4
        for (int i = 0; i < m; i++)
            proc(__shfl_sync(0xffffffffu, sv, i));
    }

    float inv = 0.125f / z;       // per-head 1/z and head-mean factor
    a0*=inv; a1*=inv; a2*=inv; a3*=inv; a4*=inv; a5*=inv; a6*=inv; a7*=inv;

    // sum over the 8 heads: V lanes with same (m&1) differ in bits 1..3
    #pragma unroll
    for (int msk = 2; msk <= 8; msk <<= 1) {
        a0 += __shfl_xor_sync(0xffffffffu, a0, msk);
        a1 += __shfl_xor_sync(0xffffffffu, a1, msk);
        a2 += __shfl_xor_sync(0xffffffffu, a2, msk);
        a3 += __shfl_xor_sync(0xffffffffu, a3, msk);
        a4 += __shfl_xor_sync(0xffffffffu, a4, msk);
        a5 += __shfl_xor_sync(0xffffffffu, a5, msk);
        a6 += __shfl_xor_sync(0xffffffffu, a6, msk);
        a7 += __shfl_xor_sync(0xffffffffu, a7, msk);
    }

    if (lane == 16 || lane == 17) {
        float4* op = reinterpret_cast<float4*>(out + n * 16 + (lane - 16) * 8);
        op[0] = make_float4(a0, a1, a2, a3);
        op[1] = make_float4(a4, a5, a6, a7);
    }
}

// ------------------------------------------------------------------
extern "C" void kernel_launch(void* const* d_in, const int* in_sizes, int n_in,
                              void* d_out, int out_size)
{
    const float* h  = (const float*)d_in[0];
    const float* Qw = (const float*)d_in[1];
    const float* Qb = (const float*)d_in[2];
    const float* Kw = (const float*)d_in[3];
    const float* Kb = (const float*)d_in[4];
    const float* Vw = (const float*)d_in[5];
    const float* Vb = (const float*)d_in[6];
    const int*  src = (const int*) d_in[7];
    const int*  dst = (const int*) d_in[8];
    float* out = (float*)d_out;

    int N  = in_sizes[0] / 128;
    int nE = in_sizes[7];
    int nb = (N + 255) / 256;

    prep_kernel<<<64, 256>>>(Qw, Qb, Kw, Kb, Vw, Vb);
    zero_cnt_kernel<<<nb, 256>>>(N);

    dim3 ggrid((N + BM - 1) / BM, 3);   // y: 0=K+Qs, 1=V, 2=edge count
    gemm_kernel<<<ggrid, 256>>>(h, dst, N, nE);

    scan_a_kernel<<<nb, 256>>>(N);
    scan_b_kernel<<<1, 256>>>(nb);
    scan_c_kernel<<<nb, 256>>>(N, nE);
    fill_kernel<<<(nE + 255) / 256, 256>>>(src, dst, nE);

    gather_kernel<<<(N + 7) / 8, 256>>>(out, N);
}

// round 12
// speedup vs baseline: 1.0583x; 1.0583x over previous
#include <cuda_runtime.h>
#include <cuda_fp16.h>
#include <math.h>

#define MAXN 50048
#define MAXE 1605632
#define NH 8
#define OD 16

// ---- device scratch ----
__device__ __half g_KV [MAXN * 256];    // [node][K(128) | V(128)] fp16
__device__ float  g_Qs [MAXN * 16];     // Qsum fp32
__device__ float  g_W  [256 * 128];     // Kw | Vw
__device__ float  g_b  [256];
__device__ float  g_Qsw[16 * 128];      // head-reduced Q weights
__device__ float  g_qb [16];
__device__ int    g_cnt[MAXN];
__device__ int    g_cur[MAXN];
__device__ int    g_ofs[MAXN + 1];
__device__ int    g_part[256];
__device__ int    g_adj[MAXE];

// ------------------------------------------------------------------
// Kernel: assemble weights
// ------------------------------------------------------------------
__global__ void prep_kernel(const float* __restrict__ Qw, const float* __restrict__ Qb,
                            const float* __restrict__ Kw, const float* __restrict__ Kb,
                            const float* __restrict__ Vw, const float* __restrict__ Vb)
{
    int t = blockIdx.x * blockDim.x + threadIdx.x;
    if (t < 128 * 128) {
        g_W[t]             = Kw[t];
        g_W[128 * 128 + t] = Vw[t];
    }
    if (t < 16 * 128) {
        int d = t / 128, c = t % 128;
        float s = 0.f;
        #pragma unroll
        for (int hh = 0; hh < NH; hh++) s += Qw[(hh * OD + d) * 128 + c];
        g_Qsw[t] = s;
    }
    if (t < 128) { g_b[t] = Kb[t]; g_b[128 + t] = Vb[t]; }
    if (t < 16) {
        float s = 0.f;
        #pragma unroll
        for (int hh = 0; hh < NH; hh++) s += Qb[hh * OD + t];
        g_qb[t] = s;
    }
}

// ------------------------------------------------------------------
// Kernel: zero CSR counters
// ------------------------------------------------------------------
__global__ void zero_cnt_kernel(int N)
{
    int i = blockIdx.x * blockDim.x + threadIdx.x;
    if (i < N) { g_cnt[i] = 0; g_cur[i] = 0; }
}

// ------------------------------------------------------------------
// GEMM  C[N,256] = h @ [Kw|Vw]^T + b  -> fp16 g_KV
//   y==0 blocks additionally compute Qsum (16 cols) reusing the A tile.
// 128x128 tile, BK=8, 8x8 micro-tile, packed fma.rn.f32x2 (FFMA2)
// ------------------------------------------------------------------
#define BM 128
#define BN 128
#define BK 8
__global__ __launch_bounds__(256) void gemm_kernel(const float* __restrict__ h, int N)
{
    __shared__ __align__(16) float As[BK][BM + 4];
    __shared__ __align__(16) float Bs[BK][BN + 4];
    __shared__ float Qb_s[BK][16];

    int tid = threadIdx.x;
    int tx = tid & 15;
    int ty = tid >> 4;
    int n0 = blockIdx.x * BM;
    int o0 = blockIdx.y * BN;
    bool doq = (blockIdx.y == 0);

    int lrow = tid >> 1;
    int lk   = (tid & 1) * 4;

    unsigned long long acc2[8][4];
    float acc_q[8];
    #pragma unroll
    for (int i = 0; i < 8; i++) {
        acc_q[i] = 0.f;
        #pragma unroll
        for (int jj = 0; jj < 4; jj++) acc2[i][jj] = 0ull;
    }

    int an = n0 + lrow; if (an >= N) an = N - 1;
    const float* aptr = h   + (size_t)an * 128 + lk;
    const float* bptr = g_W + (size_t)(o0 + lrow) * 128 + lk;

    for (int k0 = 0; k0 < 128; k0 += BK) {
        float4 av = *reinterpret_cast<const float4*>(aptr + k0);
        float4 bv = *reinterpret_cast<const float4*>(bptr + k0);
        As[lk + 0][lrow] = av.x; As[lk + 1][lrow] = av.y;
        As[lk + 2][lrow] = av.z; As[lk + 3][lrow] = av.w;
        Bs[lk + 0][lrow] = bv.x; Bs[lk + 1][lrow] = bv.y;
        Bs[lk + 2][lrow] = bv.z; Bs[lk + 3][lrow] = bv.w;
        if (doq && tid < 128) {
            int d = tid >> 3, kk = tid & 7;
            Qb_s[kk][d] = g_Qsw[d * 128 + k0 + kk];
        }
        __syncthreads();

        #pragma unroll
        for (int kk = 0; kk < BK; kk++) {
            float4 a0 = *reinterpret_cast<const float4*>(&As[kk][ty * 4]);
            float4 a1 = *reinterpret_cast<const float4*>(&As[kk][64 + ty * 4]);
            ulonglong2 bA = *reinterpret_cast<const ulonglong2*>(&Bs[kk][tx * 4]);
            ulonglong2 bB = *reinterpret_cast<const ulonglong2*>(&Bs[kk][64 + tx * 4]);
            unsigned long long B2[4] = { bA.x, bA.y, bB.x, bB.y };
            float aval[8] = { a0.x, a0.y, a0.z, a0.w, a1.x, a1.y, a1.z, a1.w };
            unsigned long long A2[8];
            #pragma unroll
            for (int i = 0; i < 8; i++)
                asm("mov.b64 %0, {%1, %1};" : "=l"(A2[i]) : "f"(aval[i]));
            #pragma unroll
            for (int i = 0; i < 8; i++)
                #pragma unroll
                for (int jj = 0; jj < 4; jj++)
                    asm("fma.rn.f32x2 %0, %1, %2, %0;"
                        : "+l"(acc2[i][jj]) : "l"(A2[i]), "l"(B2[jj]));
            if (doq) {
                float bq = Qb_s[kk][tx];
                #pragma unroll
                for (int i = 0; i < 8; i++) acc_q[i] = fmaf(aval[i], bq, acc_q[i]);
            }
        }
        __syncthreads();
    }

    #pragma unroll
    for (int i = 0; i < 8; i++) {
        int n = n0 + ((i < 4) ? (ty * 4 + i) : (64 + ty * 4 + (i - 4)));
        if (n >= N) continue;
        #pragma unroll
        for (int jj = 0; jj < 4; jj++) {
            int jb = (jj < 2) ? (tx * 4 + 2 * jj) : (64 + tx * 4 + 2 * (jj - 2));
            int o = o0 + jb;
            float lo, hi;
            asm("mov.b64 {%0, %1}, %2;" : "=f"(lo), "=f"(hi) : "l"(acc2[i][jj]));
            lo += g_b[o];
            hi += g_b[o + 1];
            *reinterpret_cast<__half2*>(&g_KV[(size_t)n * 256 + o]) =
                __floats2half2_rn(lo, hi);
        }
        if (doq) g_Qs[n * 16 + tx] = acc_q[i] + g_qb[tx];
    }
}

// ------------------------------------------------------------------
// CSR build
// ------------------------------------------------------------------
__global__ void count_kernel(const int* __restrict__ dst, int nE)
{
    int e = blockIdx.x * blockDim.x + threadIdx.x;
    if (e < nE) atomicAdd(&g_cnt[dst[e]], 1);
}

__global__ void scan_a_kernel(int N)
{
    __shared__ int sm[256];
    int tid = threadIdx.x;
    int i = blockIdx.x * 256 + tid;
    int v = (i < N) ? g_cnt[i] : 0;
    sm[tid] = v; __syncthreads();
    #pragma unroll
    for (int off = 1; off < 256; off <<= 1) {
        int t = (tid >= off) ? sm[tid - off] : 0;
        __syncthreads();
        sm[tid] += t;
        __syncthreads();
    }
    if (i < N) g_ofs[i] = sm[tid] - v;               // block-local exclusive
    if (tid == 255) g_part[blockIdx.x] = sm[255];    // block total
}

__global__ void scan_b_kernel(int nb)
{
    __shared__ int sm[256];
    int tid = threadIdx.x;
    int v = (tid < nb) ? g_part[tid] : 0;
    sm[tid] = v; __syncthreads();
    #pragma unroll
    for (int off = 1; off < 256; off <<= 1) {
        int t = (tid >= off) ? sm[tid - off] : 0;
        __syncthreads();
        sm[tid] += t;
        __syncthreads();
    }
    if (tid < nb) g_part[tid] = sm[tid] - v;         // exclusive
}

__global__ void scan_c_kernel(int N, int nE)
{
    int i = blockIdx.x * 256 + threadIdx.x;
    if (i < N) g_ofs[i] += g_part[blockIdx.x];
    if (i == 0) g_ofs[N] = nE;
}

__global__ void fill_kernel(const int* __restrict__ src, const int* __restrict__ dst, int nE)
{
    int e = blockIdx.x * blockDim.x + threadIdx.x;
    if (e < nE) {
        int d = dst[e];
        int p = g_ofs[d] + atomicAdd(&g_cur[d], 1);
        g_adj[p] = src[e];
    }
}

// ------------------------------------------------------------------
// Gather: one warp per dst node (R7-proven form).
// ------------------------------------------------------------------
__device__ __forceinline__ void edge_proc(int s, const float4& q, int lane,
                                          float4& wv, float& z)
{
    const __half* base = g_KV + (size_t)s * 256;
    uint2 kr = *reinterpret_cast<const uint2*>(base + lane * 4);
    uint2 vr = *reinterpret_cast<const uint2*>(base + 128 + lane * 4);

    float2 k0 = __half22float2(*reinterpret_cast<__half2*>(&kr.x));
    float2 k1 = __half22float2(*reinterpret_cast<__half2*>(&kr.y));
    float p = k0.x * q.x + k0.y * q.y + k1.x * q.z + k1.y * q.w;
    p += __shfl_xor_sync(0xffffffffu, p, 1);
    p += __shfl_xor_sync(0xffffffffu, p, 2);
    float sc = __expf(fminf(fmaxf(p * 0.25f, -5.f), 5.f));

    float2 v0 = __half22float2(*reinterpret_cast<__half2*>(&vr.x));
    float2 v1 = __half22float2(*reinterpret_cast<__half2*>(&vr.y));
    wv.x = fmaf(sc, v0.x, wv.x);
    wv.y = fmaf(sc, v0.y, wv.y);
    wv.z = fmaf(sc, v1.x, wv.z);
    wv.w = fmaf(sc, v1.y, wv.w);
    z += sc;
}

__global__ __launch_bounds__(256) void gather_kernel(float* __restrict__ out, int N)
{
    int n    = (blockIdx.x * blockDim.x + threadIdx.x) >> 5;
    int lane = threadIdx.x & 31;
    if (n >= N) return;

    float4 q = *reinterpret_cast<const float4*>(g_Qs + n * 16 + (lane & 3) * 4);
    float4 wv = make_float4(0.f, 0.f, 0.f, 0.f);
    float z = 0.f;

    edge_proc(n, q, lane, wv, z);   // self-loop

    int beg = g_ofs[n], end = g_ofs[n + 1];
    for (int base = beg; base < end; base += 32) {
        int rem = end - base;
        int sv = (lane < rem) ? g_adj[base + lane] : 0;
        int m = min(rem, 32);
        #pragma unroll 4
        for (int i = 0; i < m; i++) {
            int s = __shfl_sync(0xffffffffu, sv, i);
            edge_proc(s, q, lane, wv, z);
        }
    }

    float inv = 0.125f / z;
    wv.x *= inv; wv.y *= inv; wv.z *= inv; wv.w *= inv;

    #pragma unroll
    for (int m = 4; m < 32; m <<= 1) {
        wv.x += __shfl_xor_sync(0xffffffffu, wv.x, m);
        wv.y += __shfl_xor_sync(0xffffffffu, wv.y, m);
        wv.z += __shfl_xor_sync(0xffffffffu, wv.z, m);
        wv.w += __shfl_xor_sync(0xffffffffu, wv.w, m);
    }

    if (lane < 4)
        *reinterpret_cast<float4*>(out + n * 16 + lane * 4) = wv;
}

// ------------------------------------------------------------------
extern "C" void kernel_launch(void* const* d_in, const int* in_sizes, int n_in,
                              void* d_out, int out_size)
{
    const float* h  = (const float*)d_in[0];
    const float* Qw = (const float*)d_in[1];
    const float* Qb = (const float*)d_in[2];
    const float* Kw = (const float*)d_in[3];
    const float* Kb = (const float*)d_in[4];
    const float* Vw = (const float*)d_in[5];
    const float* Vb = (const float*)d_in[6];
    const int*  src = (const int*) d_in[7];
    const int*  dst = (const int*) d_in[8];
    float* out = (float*)d_out;

    int N  = in_sizes[0] / 128;
    int nE = in_sizes[7];
    int nb = (N + 255) / 256;

    prep_kernel<<<64, 256>>>(Qw, Qb, Kw, Kb, Vw, Vb);
    zero_cnt_kernel<<<nb, 256>>>(N);

    dim3 ggrid((N + BM - 1) / BM, 2);   // y: 0=K+Qsum, 1=V
    gemm_kernel<<<ggrid, 256>>>(h, N);

    count_kernel<<<(nE + 255) / 256, 256>>>(dst, nE);
    scan_a_kernel<<<nb, 256>>>(N);
    scan_b_kernel<<<1, 256>>>(nb);
    scan_c_kernel<<<nb, 256>>>(N, nE);
    fill_kernel<<<(nE + 255) / 256, 256>>>(src, dst, nE);

    gather_kernel<<<(N + 7) / 8, 256>>>(out, N);
}

// round 13
// speedup vs baseline: 1.1142x; 1.0528x over previous
#include <cuda_runtime.h>
#include <cuda_fp16.h>
#include <math.h>

#define MAXN 50048
#define MAXE 1605632
#define NH 8
#define OD 16

// ---- device scratch ----
__device__ __half g_KV [MAXN * 256];    // [node][K(128) | V(128)] fp16
__device__ float  g_Qs [MAXN * 16];     // Qsum fp32
__device__ float  g_W  [256 * 128];     // Kw | Vw
__device__ float  g_b  [256];
__device__ float  g_Qsw[16 * 128];      // head-reduced Q weights
__device__ float  g_qb [16];
__device__ int    g_cnt[MAXN];
__device__ int    g_cur[MAXN];
__device__ int    g_ofs[MAXN + 1];
__device__ int    g_part[256];
__device__ int    g_adj[MAXE];

// ------------------------------------------------------------------
// Kernel: assemble weights
// ------------------------------------------------------------------
__global__ void prep_kernel(const float* __restrict__ Qw, const float* __restrict__ Qb,
                            const float* __restrict__ Kw, const float* __restrict__ Kb,
                            const float* __restrict__ Vw, const float* __restrict__ Vb)
{
    int t = blockIdx.x * blockDim.x + threadIdx.x;
    if (t < 128 * 128) {
        g_W[t]             = Kw[t];
        g_W[128 * 128 + t] = Vw[t];
    }
    if (t < 16 * 128) {
        int d = t / 128, c = t % 128;
        float s = 0.f;
        #pragma unroll
        for (int hh = 0; hh < NH; hh++) s += Qw[(hh * OD + d) * 128 + c];
        g_Qsw[t] = s;
    }
    if (t < 128) { g_b[t] = Kb[t]; g_b[128 + t] = Vb[t]; }
    if (t < 16) {
        float s = 0.f;
        #pragma unroll
        for (int hh = 0; hh < NH; hh++) s += Qb[hh * OD + t];
        g_qb[t] = s;
    }
}

__global__ void zero_cnt_kernel(int N)
{
    int i = blockIdx.x * blockDim.x + threadIdx.x;
    if (i < N) { g_cnt[i] = 0; g_cur[i] = 0; }
}

// ------------------------------------------------------------------
// GEMM  C[N,256] = h @ [Kw|Vw]^T + b  -> fp16 g_KV   (R7-proven form)
// ------------------------------------------------------------------
#define BM 128
#define BN 128
#define BK 8
__global__ __launch_bounds__(256) void gemm_kernel(const float* __restrict__ h, int N)
{
    __shared__ __align__(16) float As[BK][BM + 4];
    __shared__ __align__(16) float Bs[BK][BN + 4];

    int tid = threadIdx.x;
    int tx = tid & 15;
    int ty = tid >> 4;
    int n0 = blockIdx.x * BM;
    int o0 = blockIdx.y * BN;

    int lrow = tid >> 1;
    int lk   = (tid & 1) * 4;

    unsigned long long acc2[8][4];
    #pragma unroll
    for (int i = 0; i < 8; i++)
        #pragma unroll
        for (int jj = 0; jj < 4; jj++) acc2[i][jj] = 0ull;

    int an = n0 + lrow; if (an >= N) an = N - 1;
    const float* aptr = h   + (size_t)an * 128 + lk;
    const float* bptr = g_W + (size_t)(o0 + lrow) * 128 + lk;

    for (int k0 = 0; k0 < 128; k0 += BK) {
        float4 av = *reinterpret_cast<const float4*>(aptr + k0);
        float4 bv = *reinterpret_cast<const float4*>(bptr + k0);
        As[lk + 0][lrow] = av.x; As[lk + 1][lrow] = av.y;
        As[lk + 2][lrow] = av.z; As[lk + 3][lrow] = av.w;
        Bs[lk + 0][lrow] = bv.x; Bs[lk + 1][lrow] = bv.y;
        Bs[lk + 2][lrow] = bv.z; Bs[lk + 3][lrow] = bv.w;
        __syncthreads();

        #pragma unroll
        for (int kk = 0; kk < BK; kk++) {
            float4 a0 = *reinterpret_cast<const float4*>(&As[kk][ty * 4]);
            float4 a1 = *reinterpret_cast<const float4*>(&As[kk][64 + ty * 4]);
            ulonglong2 bA = *reinterpret_cast<const ulonglong2*>(&Bs[kk][tx * 4]);
            ulonglong2 bB = *reinterpret_cast<const ulonglong2*>(&Bs[kk][64 + tx * 4]);
            unsigned long long B2[4] = { bA.x, bA.y, bB.x, bB.y };
            float aval[8] = { a0.x, a0.y, a0.z, a0.w, a1.x, a1.y, a1.z, a1.w };
            unsigned long long A2[8];
            #pragma unroll
            for (int i = 0; i < 8; i++)
                asm("mov.b64 %0, {%1, %1};" : "=l"(A2[i]) : "f"(aval[i]));
            #pragma unroll
            for (int i = 0; i < 8; i++)
                #pragma unroll
                for (int jj = 0; jj < 4; jj++)
                    asm("fma.rn.f32x2 %0, %1, %2, %0;"
                        : "+l"(acc2[i][jj]) : "l"(A2[i]), "l"(B2[jj]));
        }
        __syncthreads();
    }

    #pragma unroll
    for (int i = 0; i < 8; i++) {
        int n = n0 + ((i < 4) ? (ty * 4 + i) : (64 + ty * 4 + (i - 4)));
        if (n >= N) continue;
        #pragma unroll
        for (int jj = 0; jj < 4; jj++) {
            int jb = (jj < 2) ? (tx * 4 + 2 * jj) : (64 + tx * 4 + 2 * (jj - 2));
            int o = o0 + jb;
            float lo, hi;
            asm("mov.b64 {%0, %1}, %2;" : "=f"(lo), "=f"(hi) : "l"(acc2[i][jj]));
            lo += g_b[o];
            hi += g_b[o + 1];
            *reinterpret_cast<__half2*>(&g_KV[(size_t)n * 256 + o]) =
                __floats2half2_rn(lo, hi);
        }
    }
}

// ------------------------------------------------------------------
// Qsum[N,16] = h @ Qsw^T + qb  — GEMM-style tile, 128 nodes/block.
// Thread (tx=dim 0..15, ty=rowgrp 0..15) computes 8 rows × 1 dim.
// a-fragments read as LDS.128; Bq staged per k0.
// ------------------------------------------------------------------
__global__ __launch_bounds__(256) void qs_kernel(const float* __restrict__ h, int N)
{
    __shared__ __align__(16) float As[BK][BM + 4];
    __shared__ float Bq[BK][16];

    int tid = threadIdx.x;
    int tx = tid & 15;
    int ty = tid >> 4;
    int n0 = blockIdx.x * BM;

    int lrow = tid >> 1;
    int lk   = (tid & 1) * 4;

    float acc[8];
    #pragma unroll
    for (int i = 0; i < 8; i++) acc[i] = 0.f;

    int an = n0 + lrow; if (an >= N) an = N - 1;
    const float* aptr = h + (size_t)an * 128 + lk;

    for (int k0 = 0; k0 < 128; k0 += BK) {
        float4 av = *reinterpret_cast<const float4*>(aptr + k0);
        As[lk + 0][lrow] = av.x; As[lk + 1][lrow] = av.y;
        As[lk + 2][lrow] = av.z; As[lk + 3][lrow] = av.w;
        if (tid < 128) {
            int d = tid >> 3, kk = tid & 7;
            Bq[kk][d] = g_Qsw[d * 128 + k0 + kk];
        }
        __syncthreads();

        #pragma unroll
        for (int kk = 0; kk < BK; kk++) {
            float bq = Bq[kk][tx];
            float4 a0 = *reinterpret_cast<const float4*>(&As[kk][ty * 8]);
            float4 a1 = *reinterpret_cast<const float4*>(&As[kk][ty * 8 + 4]);
            acc[0] = fmaf(a0.x, bq, acc[0]);
            acc[1] = fmaf(a0.y, bq, acc[1]);
            acc[2] = fmaf(a0.z, bq, acc[2]);
            acc[3] = fmaf(a0.w, bq, acc[3]);
            acc[4] = fmaf(a1.x, bq, acc[4]);
            acc[5] = fmaf(a1.y, bq, acc[5]);
            acc[6] = fmaf(a1.z, bq, acc[6]);
            acc[7] = fmaf(a1.w, bq, acc[7]);
        }
        __syncthreads();
    }

    float qb = g_qb[tx];
    #pragma unroll
    for (int i = 0; i < 8; i++) {
        int n = n0 + ty * 8 + i;
        if (n < N) g_Qs[n * 16 + tx] = acc[i] + qb;
    }
}

// ------------------------------------------------------------------
// CSR build — ILP versions
// ------------------------------------------------------------------
__global__ void count_kernel(const int* __restrict__ dst, int nE)
{
    int e0 = (blockIdx.x * blockDim.x + threadIdx.x) * 4;
    if (e0 >= nE) return;
    if (e0 + 4 <= nE) {
        int4 d4 = *reinterpret_cast<const int4*>(dst + e0);
        atomicAdd(&g_cnt[d4.x], 1); atomicAdd(&g_cnt[d4.y], 1);
        atomicAdd(&g_cnt[d4.z], 1); atomicAdd(&g_cnt[d4.w], 1);
    } else {
        for (int e = e0; e < nE; e++) atomicAdd(&g_cnt[dst[e]], 1);
    }
}

__global__ void scan_a_kernel(int N)
{
    __shared__ int sm[256];
    int tid = threadIdx.x;
    int i = blockIdx.x * 256 + tid;
    int v = (i < N) ? g_cnt[i] : 0;
    sm[tid] = v; __syncthreads();
    #pragma unroll
    for (int off = 1; off < 256; off <<= 1) {
        int t = (tid >= off) ? sm[tid - off] : 0;
        __syncthreads();
        sm[tid] += t;
        __syncthreads();
    }
    if (i < N) g_ofs[i] = sm[tid] - v;
    if (tid == 255) g_part[blockIdx.x] = sm[255];
}

__global__ void scan_b_kernel(int nb)
{
    __shared__ int sm[256];
    int tid = threadIdx.x;
    int v = (tid < nb) ? g_part[tid] : 0;
    sm[tid] = v; __syncthreads();
    #pragma unroll
    for (int off = 1; off < 256; off <<= 1) {
        int t = (tid >= off) ? sm[tid - off] : 0;
        __syncthreads();
        sm[tid] += t;
        __syncthreads();
    }
    if (tid < nb) g_part[tid] = sm[tid] - v;
}

__global__ void scan_c_kernel(int N, int nE)
{
    int i = blockIdx.x * 256 + threadIdx.x;
    if (i < N) g_ofs[i] += g_part[blockIdx.x];
    if (i == 0) g_ofs[N] = nE;
}

__global__ void fill_kernel(const int* __restrict__ src, const int* __restrict__ dst, int nE)
{
    int e0 = (blockIdx.x * blockDim.x + threadIdx.x) * 4;
    if (e0 >= nE) return;
    if (e0 + 4 <= nE) {
        int4 s4 = *reinterpret_cast<const int4*>(src + e0);
        int4 d4 = *reinterpret_cast<const int4*>(dst + e0);
        int p0 = atomicAdd(&g_cur[d4.x], 1);
        int p1 = atomicAdd(&g_cur[d4.y], 1);
        int p2 = atomicAdd(&g_cur[d4.z], 1);
        int p3 = atomicAdd(&g_cur[d4.w], 1);
        g_adj[g_ofs[d4.x] + p0] = s4.x;
        g_adj[g_ofs[d4.y] + p1] = s4.y;
        g_adj[g_ofs[d4.z] + p2] = s4.z;
        g_adj[g_ofs[d4.w] + p3] = s4.w;
    } else {
        for (int e = e0; e < nE; e++) {
            int d = dst[e];
            int p = g_ofs[d] + atomicAdd(&g_cur[d], 1);
            g_adj[p] = src[e];
        }
    }
}

// ------------------------------------------------------------------
// Gather: one warp per dst node (R7 form + adjacency prefetch)
// ------------------------------------------------------------------
__device__ __forceinline__ void edge_proc(int s, const float4& q, int lane,
                                          float4& wv, float& z)
{
    const __half* base = g_KV + (size_t)s * 256;
    uint2 kr = *reinterpret_cast<const uint2*>(base + lane * 4);
    uint2 vr = *reinterpret_cast<const uint2*>(base + 128 + lane * 4);

    float2 k0 = __half22float2(*reinterpret_cast<__half2*>(&kr.x));
    float2 k1 = __half22float2(*reinterpret_cast<__half2*>(&kr.y));
    float p = k0.x * q.x + k0.y * q.y + k1.x * q.z + k1.y * q.w;
    p += __shfl_xor_sync(0xffffffffu, p, 1);
    p += __shfl_xor_sync(0xffffffffu, p, 2);
    float sc = __expf(fminf(fmaxf(p * 0.25f, -5.f), 5.f));

    float2 v0 = __half22float2(*reinterpret_cast<__half2*>(&vr.x));
    float2 v1 = __half22float2(*reinterpret_cast<__half2*>(&vr.y));
    wv.x = fmaf(sc, v0.x, wv.x);
    wv.y = fmaf(sc, v0.y, wv.y);
    wv.z = fmaf(sc, v1.x, wv.z);
    wv.w = fmaf(sc, v1.y, wv.w);
    z += sc;
}

__global__ __launch_bounds__(256) void gather_kernel(float* __restrict__ out, int N)
{
    int n    = (blockIdx.x * blockDim.x + threadIdx.x) >> 5;
    int lane = threadIdx.x & 31;
    if (n >= N) return;

    float4 q = *reinterpret_cast<const float4*>(g_Qs + n * 16 + (lane & 3) * 4);
    float4 wv = make_float4(0.f, 0.f, 0.f, 0.f);
    float z = 0.f;

    int beg = g_ofs[n], end = g_ofs[n + 1];
    int sv = (beg + lane < end) ? g_adj[beg + lane] : 0;

    edge_proc(n, q, lane, wv, z);   // self-loop

    for (int base = beg; base < end; base += 32) {
        int nxt = base + 32 + lane;
        int svn = (nxt < end) ? g_adj[nxt] : 0;   // prefetch next chunk
        int m = min(end - base, 32);
        #pragma unroll 4
        for (int i = 0; i < m; i++) {
            int s = __shfl_sync(0xffffffffu, sv, i);
            edge_proc(s, q, lane, wv, z);
        }
        sv = svn;
    }

    float inv = 0.125f / z;
    wv.x *= inv; wv.y *= inv; wv.z *= inv; wv.w *= inv;

    #pragma unroll
    for (int m = 4; m < 32; m <<= 1) {
        wv.x += __shfl_xor_sync(0xffffffffu, wv.x, m);
        wv.y += __shfl_xor_sync(0xffffffffu, wv.y, m);
        wv.z += __shfl_xor_sync(0xffffffffu, wv.z, m);
        wv.w += __shfl_xor_sync(0xffffffffu, wv.w, m);
    }

    if (lane < 4)
        *reinterpret_cast<float4*>(out + n * 16 + lane * 4) = wv;
}

// ------------------------------------------------------------------
extern "C" void kernel_launch(void* const* d_in, const int* in_sizes, int n_in,
                              void* d_out, int out_size)
{
    const float* h  = (const float*)d_in[0];
    const float* Qw = (const float*)d_in[1];
    const float* Qb = (const float*)d_in[2];
    const float* Kw = (const float*)d_in[3];
    const float* Kb = (const float*)d_in[4];
    const float* Vw = (const float*)d_in[5];
    const float* Vb = (const float*)d_in[6];
    const int*  src = (const int*) d_in[7];
    const int*  dst = (const int*) d_in[8];
    float* out = (float*)d_out;

    int N  = in_sizes[0] / 128;
    int nE = in_sizes[7];
    int nb = (N + 255) / 256;

    prep_kernel<<<64, 256>>>(Qw, Qb, Kw, Kb, Vw, Vb);
    zero_cnt_kernel<<<nb, 256>>>(N);

    dim3 ggrid((N + BM - 1) / BM, 2);
    gemm_kernel<<<ggrid, 256>>>(h, N);
    qs_kernel<<<(N + BM - 1) / BM, 256>>>(h, N);

    int q4 = (nE + 3) / 4;
    count_kernel<<<(q4 + 255) / 256, 256>>>(dst, nE);
    scan_a_kernel<<<nb, 256>>>(N);
    scan_b_kernel<<<1, 256>>>(nb);
    scan_c_kernel<<<nb, 256>>>(N, nE);
    fill_kernel<<<(q4 + 255) / 256, 256>>>(src, dst, nE);

    gather_kernel<<<(N + 7) / 8, 256>>>(out, N);
}

// round 14
// speedup vs baseline: 1.1159x; 1.0016x over previous
#include <cuda_runtime.h>
#include <cuda_fp16.h>
#include <math.h>

#define MAXN 50048
#define MAXE 1605632
#define NH 8
#define OD 16

// ---- device scratch ----
__device__ __half g_KV [MAXN * 256];    // [node][K(128) | V(128)] fp16
__device__ float  g_Qs [MAXN * 16];     // Qsum fp32
__device__ float  g_W  [256 * 128];     // Kw | Vw
__device__ float  g_b  [256];
__device__ float  g_Qsw[16 * 128];      // head-reduced Q weights
__device__ float  g_qb [16];
__device__ int    g_cnt[MAXN];
__device__ int    g_cur[MAXN];
__device__ int    g_ofs[MAXN + 1];
__device__ int    g_part[256];
__device__ int    g_adj[MAXE];

// ------------------------------------------------------------------
// Kernel: assemble weights
// ------------------------------------------------------------------
__global__ void prep_kernel(const float* __restrict__ Qw, const float* __restrict__ Qb,
                            const float* __restrict__ Kw, const float* __restrict__ Kb,
                            const float* __restrict__ Vw, const float* __restrict__ Vb)
{
    int t = blockIdx.x * blockDim.x + threadIdx.x;
    if (t < 128 * 128) {
        g_W[t]             = Kw[t];
        g_W[128 * 128 + t] = Vw[t];
    }
    if (t < 16 * 128) {
        int d = t / 128, c = t % 128;
        float s = 0.f;
        #pragma unroll
        for (int hh = 0; hh < NH; hh++) s += Qw[(hh * OD + d) * 128 + c];
        g_Qsw[t] = s;
    }
    if (t < 128) { g_b[t] = Kb[t]; g_b[128 + t] = Vb[t]; }
    if (t < 16) {
        float s = 0.f;
        #pragma unroll
        for (int hh = 0; hh < NH; hh++) s += Qb[hh * OD + t];
        g_qb[t] = s;
    }
}

__global__ void zero_cnt_kernel(int N)
{
    int i = blockIdx.x * blockDim.x + threadIdx.x;
    if (i < N) { g_cnt[i] = 0; g_cur[i] = 0; }
}

// ------------------------------------------------------------------
// GEMM  C[N,256] = h @ [Kw|Vw]^T + b  -> fp16 g_KV
// R7 form + register double-buffering of the global loads.
// ------------------------------------------------------------------
#define BM 128
#define BN 128
#define BK 8
__global__ __launch_bounds__(256) void gemm_kernel(const float* __restrict__ h, int N)
{
    __shared__ __align__(16) float As[BK][BM + 4];
    __shared__ __align__(16) float Bs[BK][BN + 4];

    int tid = threadIdx.x;
    int tx = tid & 15;
    int ty = tid >> 4;
    int n0 = blockIdx.x * BM;
    int o0 = blockIdx.y * BN;

    int lrow = tid >> 1;
    int lk   = (tid & 1) * 4;

    unsigned long long acc2[8][4];
    #pragma unroll
    for (int i = 0; i < 8; i++)
        #pragma unroll
        for (int jj = 0; jj < 4; jj++) acc2[i][jj] = 0ull;

    int an = n0 + lrow; if (an >= N) an = N - 1;
    const float* aptr = h   + (size_t)an * 128 + lk;
    const float* bptr = g_W + (size_t)(o0 + lrow) * 128 + lk;

    float4 av = *reinterpret_cast<const float4*>(aptr);
    float4 bv = *reinterpret_cast<const float4*>(bptr);

    for (int k0 = 0; k0 < 128; k0 += BK) {
        As[lk + 0][lrow] = av.x; As[lk + 1][lrow] = av.y;
        As[lk + 2][lrow] = av.z; As[lk + 3][lrow] = av.w;
        Bs[lk + 0][lrow] = bv.x; Bs[lk + 1][lrow] = bv.y;
        Bs[lk + 2][lrow] = bv.z; Bs[lk + 3][lrow] = bv.w;

        if (k0 + BK < 128) {        // prefetch next tile (overlaps compute)
            av = *reinterpret_cast<const float4*>(aptr + k0 + BK);
            bv = *reinterpret_cast<const float4*>(bptr + k0 + BK);
        }
        __syncthreads();

        #pragma unroll
        for (int kk = 0; kk < BK; kk++) {
            float4 a0 = *reinterpret_cast<const float4*>(&As[kk][ty * 4]);
            float4 a1 = *reinterpret_cast<const float4*>(&As[kk][64 + ty * 4]);
            ulonglong2 bA = *reinterpret_cast<const ulonglong2*>(&Bs[kk][tx * 4]);
            ulonglong2 bB = *reinterpret_cast<const ulonglong2*>(&Bs[kk][64 + tx * 4]);
            unsigned long long B2[4] = { bA.x, bA.y, bB.x, bB.y };
            float aval[8] = { a0.x, a0.y, a0.z, a0.w, a1.x, a1.y, a1.z, a1.w };
            unsigned long long A2[8];
            #pragma unroll
            for (int i = 0; i < 8; i++)
                asm("mov.b64 %0, {%1, %1};" : "=l"(A2[i]) : "f"(aval[i]));
            #pragma unroll
            for (int i = 0; i < 8; i++)
                #pragma unroll
                for (int jj = 0; jj < 4; jj++)
                    asm("fma.rn.f32x2 %0, %1, %2, %0;"
                        : "+l"(acc2[i][jj]) : "l"(A2[i]), "l"(B2[jj]));
        }
        __syncthreads();
    }

    #pragma unroll
    for (int i = 0; i < 8; i++) {
        int n = n0 + ((i < 4) ? (ty * 4 + i) : (64 + ty * 4 + (i - 4)));
        if (n >= N) continue;
        #pragma unroll
        for (int jj = 0; jj < 4; jj++) {
            int jb = (jj < 2) ? (tx * 4 + 2 * jj) : (64 + tx * 4 + 2 * (jj - 2));
            int o = o0 + jb;
            float lo, hi;
            asm("mov.b64 {%0, %1}, %2;" : "=f"(lo), "=f"(hi) : "l"(acc2[i][jj]));
            lo += g_b[o];
            hi += g_b[o + 1];
            *reinterpret_cast<__half2*>(&g_KV[(size_t)n * 256 + o]) =
                __floats2half2_rn(lo, hi);
        }
    }
}

// ------------------------------------------------------------------
// Qsum v3: one thread per node. 32 unrolled LDG.128 over own h row
// (high per-thread MLP), FFMA2 accumulation, Wt broadcast from smem.
// ------------------------------------------------------------------
__global__ __launch_bounds__(256) void qs_kernel(const float* __restrict__ h, int N)
{
    __shared__ __align__(16) float Wt[128][16];   // [k][d], 8KB
    int tid = threadIdx.x;
    #pragma unroll
    for (int t = tid; t < 16 * 128; t += 256) {
        int d = t >> 7, k = t & 127;
        Wt[k][d] = g_Qsw[t];
    }
    __syncthreads();

    int n = blockIdx.x * 256 + tid;
    if (n >= N) return;

    const float4* hp = reinterpret_cast<const float4*>(h + (size_t)n * 128);
    unsigned long long acc2[8];
    #pragma unroll
    for (int j = 0; j < 8; j++) acc2[j] = 0ull;

    #pragma unroll 8
    for (int k4 = 0; k4 < 32; k4++) {
        float4 hv = hp[k4];
        float a[4] = { hv.x, hv.y, hv.z, hv.w };
        #pragma unroll
        for (int u = 0; u < 4; u++) {
            int k = k4 * 4 + u;
            unsigned long long a2;
            asm("mov.b64 %0, {%1, %1};" : "=l"(a2) : "f"(a[u]));
            const unsigned long long* wp =
                reinterpret_cast<const unsigned long long*>(&Wt[k][0]);
            #pragma unroll
            for (int j = 0; j < 8; j++)
                asm("fma.rn.f32x2 %0, %1, %2, %0;"
                    : "+l"(acc2[j]) : "l"(a2), "l"(wp[j]));
        }
    }

    float o[16];
    #pragma unroll
    for (int j = 0; j < 8; j++) {
        float lo, hi;
        asm("mov.b64 {%0, %1}, %2;" : "=f"(lo), "=f"(hi) : "l"(acc2[j]));
        o[2 * j]     = lo + g_qb[2 * j];
        o[2 * j + 1] = hi + g_qb[2 * j + 1];
    }
    float4* op = reinterpret_cast<float4*>(g_Qs + (size_t)n * 16);
    op[0] = make_float4(o[0],  o[1],  o[2],  o[3]);
    op[1] = make_float4(o[4],  o[5],  o[6],  o[7]);
    op[2] = make_float4(o[8],  o[9],  o[10], o[11]);
    op[3] = make_float4(o[12], o[13], o[14], o[15]);
}

// ------------------------------------------------------------------
// CSR build — ILP versions
// ------------------------------------------------------------------
__global__ void count_kernel(const int* __restrict__ dst, int nE)
{
    int e0 = (blockIdx.x * blockDim.x + threadIdx.x) * 4;
    if (e0 >= nE) return;
    if (e0 + 4 <= nE) {
        int4 d4 = *reinterpret_cast<const int4*>(dst + e0);
        atomicAdd(&g_cnt[d4.x], 1); atomicAdd(&g_cnt[d4.y], 1);
        atomicAdd(&g_cnt[d4.z], 1); atomicAdd(&g_cnt[d4.w], 1);
    } else {
        for (int e = e0; e < nE; e++) atomicAdd(&g_cnt[dst[e]], 1);
    }
}

__global__ void scan_a_kernel(int N)
{
    __shared__ int sm[256];
    int tid = threadIdx.x;
    int i = blockIdx.x * 256 + tid;
    int v = (i < N) ? g_cnt[i] : 0;
    sm[tid] = v; __syncthreads();
    #pragma unroll
    for (int off = 1; off < 256; off <<= 1) {
        int t = (tid >= off) ? sm[tid - off] : 0;
        __syncthreads();
        sm[tid] += t;
        __syncthreads();
    }
    if (i < N) g_ofs[i] = sm[tid] - v;
    if (tid == 255) g_part[blockIdx.x] = sm[255];
}

__global__ void scan_b_kernel(int nb)
{
    __shared__ int sm[256];
    int tid = threadIdx.x;
    int v = (tid < nb) ? g_part[tid] : 0;
    sm[tid] = v; __syncthreads();
    #pragma unroll
    for (int off = 1; off < 256; off <<= 1) {
        int t = (tid >= off) ? sm[tid - off] : 0;
        __syncthreads();
        sm[tid] += t;
        __syncthreads();
    }
    if (tid < nb) g_part[tid] = sm[tid] - v;
}

__global__ void scan_c_kernel(int N, int nE)
{
    int i = blockIdx.x * 256 + threadIdx.x;
    if (i < N) g_ofs[i] += g_part[blockIdx.x];
    if (i == 0) g_ofs[N] = nE;
}

__global__ void fill_kernel(const int* __restrict__ src, const int* __restrict__ dst, int nE)
{
    int e0 = (blockIdx.x * blockDim.x + threadIdx.x) * 4;
    if (e0 >= nE) return;
    if (e0 + 4 <= nE) {
        int4 s4 = *reinterpret_cast<const int4*>(src + e0);
        int4 d4 = *reinterpret_cast<const int4*>(dst + e0);
        int p0 = atomicAdd(&g_cur[d4.x], 1);
        int p1 = atomicAdd(&g_cur[d4.y], 1);
        int p2 = atomicAdd(&g_cur[d4.z], 1);
        int p3 = atomicAdd(&g_cur[d4.w], 1);
        g_adj[g_ofs[d4.x] + p0] = s4.x;
        g_adj[g_ofs[d4.y] + p1] = s4.y;
        g_adj[g_ofs[d4.z] + p2] = s4.z;
        g_adj[g_ofs[d4.w] + p3] = s4.w;
    } else {
        for (int e = e0; e < nE; e++) {
            int d = dst[e];
            int p = g_ofs[d] + atomicAdd(&g_cur[d], 1);
            g_adj[p] = src[e];
        }
    }
}

// ------------------------------------------------------------------
// Gather: one warp per dst node (R7 form + adjacency prefetch)
// ------------------------------------------------------------------
__device__ __forceinline__ void edge_proc(int s, const float4& q, int lane,
                                          float4& wv, float& z)
{
    const __half* base = g_KV + (size_t)s * 256;
    uint2 kr = *reinterpret_cast<const uint2*>(base + lane * 4);
    uint2 vr = *reinterpret_cast<const uint2*>(base + 128 + lane * 4);

    float2 k0 = __half22float2(*reinterpret_cast<__half2*>(&kr.x));
    float2 k1 = __half22float2(*reinterpret_cast<__half2*>(&kr.y));
    float p = k0.x * q.x + k0.y * q.y + k1.x * q.z + k1.y * q.w;
    p += __shfl_xor_sync(0xffffffffu, p, 1);
    p += __shfl_xor_sync(0xffffffffu, p, 2);
    float sc = __expf(fminf(fmaxf(p * 0.25f, -5.f), 5.f));

    float2 v0 = __half22float2(*reinterpret_cast<__half2*>(&vr.x));
    float2 v1 = __half22float2(*reinterpret_cast<__half2*>(&vr.y));
    wv.x = fmaf(sc, v0.x, wv.x);
    wv.y = fmaf(sc, v0.y, wv.y);
    wv.z = fmaf(sc, v1.x, wv.z);
    wv.w = fmaf(sc, v1.y, wv.w);
    z += sc;
}

__global__ __launch_bounds__(256) void gather_kernel(float* __restrict__ out, int N)
{
    int n    = (blockIdx.x * blockDim.x + threadIdx.x) >> 5;
    int lane = threadIdx.x & 31;
    if (n >= N) return;

    float4 q = *reinterpret_cast<const float4*>(g_Qs + n * 16 + (lane & 3) * 4);
    float4 wv = make_float4(0.f, 0.f, 0.f, 0.f);
    float z = 0.f;

    int beg = g_ofs[n], end = g_ofs[n + 1];
    int sv = (beg + lane < end) ? g_adj[beg + lane] : 0;

    edge_proc(n, q, lane, wv, z);   // self-loop

    for (int base = beg; base < end; base += 32) {
        int nxt = base + 32 + lane;
        int svn = (nxt < end) ? g_adj[nxt] : 0;   // prefetch next chunk
        int m = min(end - base, 32);
        #pragma unroll 4
        for (int i = 0; i < m; i++) {
            int s = __shfl_sync(0xffffffffu, sv, i);
            edge_proc(s, q, lane, wv, z);
        }
        sv = svn;
    }

    float inv = 0.125f / z;
    wv.x *= inv; wv.y *= inv; wv.z *= inv; wv.w *= inv;

    #pragma unroll
    for (int m = 4; m < 32; m <<= 1) {
        wv.x += __shfl_xor_sync(0xffffffffu, wv.x, m);
        wv.y += __shfl_xor_sync(0xffffffffu, wv.y, m);
        wv.z += __shfl_xor_sync(0xffffffffu, wv.z, m);
        wv.w += __shfl_xor_sync(0xffffffffu, wv.w, m);
    }

    if (lane < 4)
        *reinterpret_cast<float4*>(out + n * 16 + lane * 4) = wv;
}

// ------------------------------------------------------------------
extern "C" void kernel_launch(void* const* d_in, const int* in_sizes, int n_in,
                              void* d_out, int out_size)
{
    const float* h  = (const float*)d_in[0];
    const float* Qw = (const float*)d_in[1];
    const float* Qb = (const float*)d_in[2];
    const float* Kw = (const float*)d_in[3];
    const float* Kb = (const float*)d_in[4];
    const float* Vw = (const float*)d_in[5];
    const float* Vb = (const float*)d_in[6];
    const int*  src = (const int*) d_in[7];
    const int*  dst = (const int*) d_in[8];
    float* out = (float*)d_out;

    int N  = in_sizes[0] / 128;
    int nE = in_sizes[7];
    int nb = (N + 255) / 256;

    prep_kernel<<<64, 256>>>(Qw, Qb, Kw, Kb, Vw, Vb);
    zero_cnt_kernel<<<nb, 256>>>(N);

    dim3 ggrid((N + BM - 1) / BM, 2);
    gemm_kernel<<<ggrid, 256>>>(h, N);
    qs_kernel<<<nb, 256>>>(h, N);

    int q4 = (nE + 3) / 4;
    count_kernel<<<(q4 + 255) / 256, 256>>>(dst, nE);
    scan_a_kernel<<<nb, 256>>>(N);
    scan_b_kernel<<<1, 256>>>(nb);
    scan_c_kernel<<<nb, 256>>>(N, nE);
    fill_kernel<<<(q4 + 255) / 256, 256>>>(src, dst, nE);

    gather_kernel<<<(N + 7) / 8, 256>>>(out, N);
}